// round 11
// baseline (speedup 1.0000x reference)
#include <cuda_runtime.h>
#include <cstdint>

#define SDIM   128
#define VDIM   352           // 64*3 + 32*5
#define DIM    480
#define RPB    4             // rows per chunk
#define NTHR   128
#define NVTOT  (RPB * 88)    // 352 float4 in vector region per chunk
#define EPS    1e-5f

__device__ __forceinline__ float4 ldcs_f4(const float4* p) {
    float4 v;
    asm volatile("ld.global.cs.v4.f32 {%0,%1,%2,%3}, [%4];"
                 : "=f"(v.x), "=f"(v.y), "=f"(v.z), "=f"(v.w) : "l"(p));
    return v;
}
__device__ __forceinline__ void stcs_f4(float4* p, float4 v) {
    asm volatile("st.global.cs.v4.f32 [%0], {%1,%2,%3,%4};"
                 :: "l"(p), "f"(v.x), "f"(v.y), "f"(v.z), "f"(v.w));
}
__device__ __forceinline__ void cp16(uint32_t s, const float4* g) {
    asm volatile("cp.async.cg.shared.global [%0], [%1], 16;" :: "r"(s), "l"(g));
}
#define CP_COMMIT() asm volatile("cp.async.commit_group;" ::: "memory")
#define CP_WAIT1()  asm volatile("cp.async.wait_group 1;"  ::: "memory")

// issue the vector-region prefetch for one chunk into smem buffer `buf`
__device__ __forceinline__ void prefetch_vec(
    const float* __restrict__ x, long long row0,
    uint32_t vbase, int buf, int tid)
{
    #pragma unroll
    for (int k = 0; k < 3; k++) {
        int idx = tid + NTHR * k;
        if (idx < NVTOT) {
            int r = idx / 88, j = idx - r * 88;
            cp16(vbase + (uint32_t)(buf * NVTOT + idx) * 16u,
                 (const float4*)(x + (row0 + r) * DIM + SDIM) + j);
        }
    }
}

__global__ __launch_bounds__(NTHR) void eln_kernel(
    const float* __restrict__ x,
    const float* __restrict__ weight,
    const float* __restrict__ bias,
    float* __restrict__ out,
    int nChunks)
{
    __shared__ float4 vec[2][NVTOT];   // 11.3 KB double buffer
    const uint32_t vbase = (uint32_t)__cvta_generic_to_shared(vec);

    const int tid  = threadIdx.x;
    const int lane = tid & 31;
    const int wrp  = tid >> 5;
    const int stride = gridDim.x;

    const float4 w4 = __ldg((const float4*)weight + lane);
    const float4 b4 = __ldg((const float4*)bias   + lane);

    long long c = blockIdx.x;
    float4 sv;
    if (c < nChunks) {
        prefetch_vec(x, c * RPB, vbase, 0, tid);
        sv = ldcs_f4((const float4*)(x + (c * RPB + wrp) * DIM) + lane);
    }
    CP_COMMIT();
    int buf = 0;

    while (c < nChunks) {
        // ---- prefetch next chunk (smem, zero reg cost) ----
        const long long cn = c + stride;
        float4 svn;
        if (cn < nChunks) {
            prefetch_vec(x, cn * RPB, vbase, buf ^ 1, tid);
            svn = ldcs_f4((const float4*)(x + (cn * RPB + wrp) * DIM) + lane);
        }
        CP_COMMIT();

        const long long row0 = c * RPB;

        // ---- scalar layernorm: warp-local, independent of cp.async ----
        float sum = sv.x + sv.y + sv.z + sv.w;
        float sq  = sv.x * sv.x + sv.y * sv.y + sv.z * sv.z + sv.w * sv.w;
        #pragma unroll
        for (int o = 16; o; o >>= 1) {
            sum += __shfl_xor_sync(0xFFFFFFFFu, sum, o);
            sq  += __shfl_xor_sync(0xFFFFFFFFu, sq,  o);
        }
        const float m  = sum * (1.0f / 128.0f);
        const float rs = rsqrtf(sq * (1.0f / 128.0f) - m * m + EPS);
        float4 so;
        so.x = (sv.x - m) * rs * w4.x + b4.x;
        so.y = (sv.y - m) * rs * w4.y + b4.y;
        so.z = (sv.z - m) * rs * w4.z + b4.z;
        so.w = (sv.w - m) * rs * w4.w + b4.w;
        stcs_f4((float4*)(out + (row0 + wrp) * DIM) + lane, so);

        // ---- wait for THIS chunk's vector data (1 group may stay in flight) ----
        CP_WAIT1();
        __syncthreads();

        // ---- segment norms in smem buffer `buf`: 384 segments, 3/thread ----
        float* vb = (float*)vec[buf];
        #pragma unroll
        for (int k = 0; k < 3; k++) {
            int s = tid + NTHR * k;       // 0..383
            int r = s / 96, k96 = s - r * 96;
            if (k96 < 64) {
                float* p = vb + r * VDIM + 3 * k96;
                float a = p[0], b = p[1], cc = p[2];
                float sm = (a + b + cc) * (1.0f / 3.0f);
                float da = a - sm, db = b - sm, dc = cc - sm;
                float rr = rsqrtf((da * da + db * db + dc * dc) * (1.0f / 3.0f) + EPS);
                p[0] = da * rr; p[1] = db * rr; p[2] = dc * rr;
            } else {
                float* p = vb + r * VDIM + 192 + 5 * (k96 - 64);
                float a = p[0], b = p[1], cc = p[2], d = p[3], e = p[4];
                float sm = (a + b + cc + d + e) * 0.2f;
                float da = a - sm, db = b - sm, dc = cc - sm, dd = d - sm, de = e - sm;
                float rr = rsqrtf((da * da + db * db + dc * dc + dd * dd + de * de) * 0.2f + EPS);
                p[0] = da * rr; p[1] = db * rr; p[2] = dc * rr; p[3] = dd * rr; p[4] = de * rr;
            }
        }
        __syncthreads();

        // ---- vector region stores from smem ----
        #pragma unroll
        for (int k = 0; k < 3; k++) {
            int idx = tid + NTHR * k;
            if (idx < NVTOT) {
                int r = idx / 88, j = idx - r * 88;
                stcs_f4((float4*)(out + (row0 + r) * DIM + SDIM) + j, vec[buf][idx]);
            }
        }
        __syncthreads();   // WAR: next iter's cp.async refills this buffer

        // ---- rotate ----
        sv = svn;
        buf ^= 1;
        c = cn;
    }
}

extern "C" void kernel_launch(void* const* d_in, const int* in_sizes, int n_in,
                              void* d_out, int out_size)
{
    const float* x      = (const float*)d_in[0];
    const float* weight = (const float*)d_in[1];
    const float* bias   = (const float*)d_in[2];
    float* out = (float*)d_out;

    const int n_rows  = in_sizes[0] / DIM;   // 262144
    const int nChunks = n_rows / RPB;        // 65536
    const int grid    = 148 * 12;            // persistent, 12 CTAs/SM target
    eln_kernel<<<grid, NTHR>>>(x, weight, bias, out, nChunks);
}

// round 12
// speedup vs baseline: 1.1845x; 1.1845x over previous
#include <cuda_runtime.h>

#define SDIM   128
#define VDIM   352           // 64*3 + 32*5
#define DIM    480
#define RPB    4             // rows per block
#define NTHR   128
#define NVTOT  (RPB * 88)    // 352 float4 in vector region
#define EPS    1e-5f

__device__ __forceinline__ float4 ldcs_f4(const float4* p) {
    float4 v;
    asm volatile("ld.global.cs.v4.f32 {%0,%1,%2,%3}, [%4];"
                 : "=f"(v.x), "=f"(v.y), "=f"(v.z), "=f"(v.w) : "l"(p));
    return v;
}
__device__ __forceinline__ void stcs_f4(float4* p, float4 v) {
    asm volatile("st.global.cs.v4.f32 [%0], {%1,%2,%3,%4};"
                 :: "l"(p), "f"(v.x), "f"(v.y), "f"(v.z), "f"(v.w));
}
__device__ __forceinline__ void stcs_f(float* p, float v) {
    asm volatile("st.global.cs.f32 [%0], %1;" :: "l"(p), "f"(v));
}

__global__ __launch_bounds__(NTHR) void eln_kernel(
    const float* __restrict__ x,
    const float* __restrict__ weight,
    const float* __restrict__ bias,
    float* __restrict__ out)
{
    __shared__ float vec[RPB][VDIM];   // 5.6 KB

    const int tid  = threadIdx.x;
    const int lane = tid & 31;
    const int wrp  = tid >> 5;
    const long long row0 = (long long)blockIdx.x * RPB;

    // ---- front-batch ALL loads ----
    const float4 w4 = __ldg((const float4*)weight + lane);
    const float4 b4 = __ldg((const float4*)bias   + lane);

    // warp w owns row (row0+w)'s scalar region: 32 x LDG.128
    const float4 sv = ldcs_f4((const float4*)(x + (row0 + wrp) * DIM) + lane);

    // vector region: 4 rows x 88 float4 = 352, strided by 128 threads
    float4 v[3];
    #pragma unroll
    for (int k = 0; k < 3; k++) {
        int idx = tid + NTHR * k;
        if (idx < NVTOT) {
            int r = idx / 88, j = idx - r * 88;
            v[k] = ldcs_f4((const float4*)(x + (row0 + r) * DIM + SDIM) + j);
        }
    }

    // ---- scalar layernorm: warp-local, no barrier ----
    float sum = sv.x + sv.y + sv.z + sv.w;
    float sq  = sv.x * sv.x + sv.y * sv.y + sv.z * sv.z + sv.w * sv.w;
    #pragma unroll
    for (int o = 16; o; o >>= 1) {
        sum += __shfl_xor_sync(0xFFFFFFFFu, sum, o);
        sq  += __shfl_xor_sync(0xFFFFFFFFu, sq,  o);
    }
    const float m  = sum * (1.0f / 128.0f);
    const float rs = rsqrtf(sq * (1.0f / 128.0f) - m * m + EPS);
    float4 so;
    so.x = (sv.x - m) * rs * w4.x + b4.x;
    so.y = (sv.y - m) * rs * w4.y + b4.y;
    so.z = (sv.z - m) * rs * w4.z + b4.z;
    so.w = (sv.w - m) * rs * w4.w + b4.w;
    stcs_f4((float4*)(out + (row0 + wrp) * DIM) + lane, so);

    // ---- stage vector region into smem (conflict-free STS.128) ----
    #pragma unroll
    for (int k = 0; k < 3; k++) {
        int idx = tid + NTHR * k;
        if (idx < NVTOT) ((float4*)vec)[idx] = v[k];
    }
    __syncthreads();   // the ONLY barrier

    // ---- segment norms: read smem strided, normalize in regs,
    //      store DIRECTLY to global (coalesced strided STG.32) ----
    #pragma unroll
    for (int k = 0; k < 3; k++) {
        int s = tid + NTHR * k;           // 0..383
        int r = s / 96, k96 = s - r * 96;
        float* og = out + (row0 + r) * DIM + SDIM;
        if (k96 < 64) {
            const float* p = &vec[r][3 * k96];
            float a = p[0], b = p[1], c = p[2];
            float sm = (a + b + c) * (1.0f / 3.0f);
            float da = a - sm, db = b - sm, dc = c - sm;
            float rr = rsqrtf((da * da + db * db + dc * dc) * (1.0f / 3.0f) + EPS);
            float* q = og + 3 * k96;
            stcs_f(q + 0, da * rr);
            stcs_f(q + 1, db * rr);
            stcs_f(q + 2, dc * rr);
        } else {
            const float* p = &vec[r][192 + 5 * (k96 - 64)];
            float a = p[0], b = p[1], c = p[2], d = p[3], e = p[4];
            float sm = (a + b + c + d + e) * 0.2f;
            float da = a - sm, db = b - sm, dc = c - sm, dd = d - sm, de = e - sm;
            float rr = rsqrtf((da * da + db * db + dc * dc + dd * dd + de * de) * 0.2f + EPS);
            float* q = og + 192 + 5 * (k96 - 64);
            stcs_f(q + 0, da * rr);
            stcs_f(q + 1, db * rr);
            stcs_f(q + 2, dc * rr);
            stcs_f(q + 3, dd * rr);
            stcs_f(q + 4, de * rr);
        }
    }
}

extern "C" void kernel_launch(void* const* d_in, const int* in_sizes, int n_in,
                              void* d_out, int out_size)
{
    const float* x      = (const float*)d_in[0];
    const float* weight = (const float*)d_in[1];
    const float* bias   = (const float*)d_in[2];
    float* out = (float*)d_out;

    const int n_rows = in_sizes[0] / DIM;   // 262144
    eln_kernel<<<n_rows / RPB, NTHR>>>(x, weight, bias, out);
}